// round 4
// baseline (speedup 1.0000x reference)
#include <cuda_runtime.h>
#include <cuda_bf16.h>
#include <cstddef>

#define NBATCH 64
#define LSEQ   256
#define LASP   8
#define EMB    300
#define KP     320
#define HID    384
#define G4     1536
#define DFEAT  768
#define FIN    768
#define NCLS   3
#define SROWS  (NBATCH*LSEQ)
#define AROWS  (NBATCH*LASP)
#define MROWS  (SROWS+AROWS)

// ---------------- device scratch (static; no runtime allocation) ----------------
__device__ float g_X[MROWS * KP];
__device__ float g_xg[2 * MROWS * G4];
__device__ float g_Wt[2 * KP * G4];
__device__ float g_bias[2 * G4];
__device__ float g_W1t[FIN * FIN];
__device__ float g_W2t[FIN * FIN];
__device__ float g_Wft[FIN * 64];
__device__ float g_feat[(size_t)SROWS * DFEAT];
__device__ float g_h[2 * 2 * NBATCH * HID];
__device__ float g_aspv[NBATCH * DFEAT];
__device__ float g_dot[NBATCH * LSEQ];
__device__ float g_att[NBATCH * LSEQ];
__device__ float g_pool[NBATCH * DFEAT];
__device__ float g_x1[NBATCH * FIN];
__device__ float g_x2[NBATCH * FIN];
__device__ float g_logits[NBATCH * NCLS];
__device__ unsigned int g_bar;

__device__ __forceinline__ float sigf(float x) { return 1.0f / (1.0f + __expf(-x)); }

// ---------------- prep: weight transposes, bias sums, barrier reset ----------------
__global__ void k_prep(const float* __restrict__ wih_f, const float* __restrict__ wih_b,
                       const float* __restrict__ bih_f, const float* __restrict__ bhh_f,
                       const float* __restrict__ bih_b, const float* __restrict__ bhh_b,
                       const float* __restrict__ W1, const float* __restrict__ W2,
                       const float* __restrict__ Wf)
{
    int tid = blockIdx.x * blockDim.x + threadIdx.x;
    int stride = gridDim.x * blockDim.x;
    for (int i = tid; i < 2 * KP * G4; i += stride) {
        int d = i / (KP * G4);
        int r = i - d * (KP * G4);
        int k = r / G4, g = r - (r / G4) * G4;
        const float* w = d ? wih_b : wih_f;
        g_Wt[i] = (k < EMB) ? w[g * EMB + k] : 0.0f;
    }
    for (int i = tid; i < 2 * G4; i += stride) {
        int d = i / G4, g = i - d * G4;
        g_bias[i] = d ? (bih_b[g] + bhh_b[g]) : (bih_f[g] + bhh_f[g]);
    }
    for (int i = tid; i < FIN * FIN; i += stride) {
        int k = i / FIN, n = i - (i / FIN) * FIN;
        g_W1t[i] = W1[n * FIN + k];
        g_W2t[i] = W2[n * FIN + k];
    }
    for (int i = tid; i < FIN * 64; i += stride) {
        int k = i / 64, c = i - (i / 64) * 64;
        g_Wft[i] = (c < NCLS) ? Wf[c * FIN + k] : 0.0f;
    }
    if (tid == 0) g_bar = 0u;
}

// ---------------- gather embeddings (padded) + zero h state ----------------
__global__ void k_gather(const int* __restrict__ sentence, const int* __restrict__ aspect,
                         const float* __restrict__ emb)
{
    int tid = blockIdx.x * blockDim.x + threadIdx.x;
    int stride = gridDim.x * blockDim.x;
    for (int i = tid; i < MROWS * KP; i += stride) {
        int row = i / KP, k = i - row * KP;
        int tok = (row < SROWS) ? sentence[row] : aspect[row - SROWS];
        g_X[i] = (k < EMB) ? emb[(size_t)tok * EMB + k] : 0.0f;
    }
    for (int i = tid; i < 2 * 2 * NBATCH * HID; i += stride) g_h[i] = 0.0f;
}

// ---------------- generic fp32 GEMM: C = [relu](A[M,K] @ Bt[K,N] + bias) ----------------
#define BM 128
#define BN 64
#define BK 16

__global__ void __launch_bounds__(256) k_gemm(
    const float* __restrict__ A, int lda,
    const float* __restrict__ Bt, int ldb,
    const float* __restrict__ bias,
    float* __restrict__ C, int ldc,
    int M, int Nn, int K, int relu)
{
    __shared__ float As[BK][BM + 4];
    __shared__ float Bs[BK][BN + 4];
    int t = threadIdx.x;
    int tx = t & 15, ty = t >> 4;
    int m0 = blockIdx.x * BM, n0 = blockIdx.y * BN;
    float acc[8][4];
#pragma unroll
    for (int i = 0; i < 8; i++)
#pragma unroll
        for (int j = 0; j < 4; j++) acc[i][j] = 0.0f;

    int nkt = K / BK;
    for (int kt = 0; kt < nkt; ++kt) {
        int k0 = kt * BK;
        float4 av[2];
#pragma unroll
        for (int q = 0; q < 2; q++) {
            int f = t + 256 * q;
            int row = f >> 2, kq = (f & 3) * 4;
            int gm = m0 + row;
            av[q] = (gm < M) ? *(const float4*)(A + (size_t)gm * lda + k0 + kq)
                             : make_float4(0.f, 0.f, 0.f, 0.f);
        }
        float4 bv;
        {
            int kk = t >> 4, nq = (t & 15) * 4;
            bv = *(const float4*)(Bt + (size_t)(k0 + kk) * ldb + n0 + nq);
        }
        __syncthreads();
#pragma unroll
        for (int q = 0; q < 2; q++) {
            int f = t + 256 * q;
            int row = f >> 2, kq = (f & 3) * 4;
            As[kq + 0][row] = av[q].x; As[kq + 1][row] = av[q].y;
            As[kq + 2][row] = av[q].z; As[kq + 3][row] = av[q].w;
        }
        {
            int kk = t >> 4, nq = (t & 15) * 4;
            *(float4*)&Bs[kk][nq] = bv;
        }
        __syncthreads();
#pragma unroll
        for (int k = 0; k < BK; k++) {
            float4 b4 = *(float4*)&Bs[k][tx * 4];
            float4 a0 = *(float4*)&As[k][ty * 8];
            float4 a1 = *(float4*)&As[k][ty * 8 + 4];
            float a[8] = {a0.x, a0.y, a0.z, a0.w, a1.x, a1.y, a1.z, a1.w};
            float b[4] = {b4.x, b4.y, b4.z, b4.w};
#pragma unroll
            for (int i = 0; i < 8; i++)
#pragma unroll
                for (int j = 0; j < 4; j++)
                    acc[i][j] = fmaf(a[i], b[j], acc[i][j]);
        }
        __syncthreads();
    }
#pragma unroll
    for (int i = 0; i < 8; i++) {
        int gm = m0 + ty * 8 + i;
        if (gm < M) {
#pragma unroll
            for (int j = 0; j < 4; j++) {
                int gn = n0 + tx * 4 + j;
                if (gn < Nn) {
                    float v = acc[i][j];
                    if (bias) v += bias[gn];
                    if (relu) v = fmaxf(v, 0.0f);
                    C[(size_t)gm * ldc + gn] = v;
                }
            }
        }
    }
}

// ---------------- persistent BiLSTM recurrence ----------------
// 128 CTAs: cta = dir*64 + slice; slice owns hidden units [slice*6, slice*6+6).
// w_hh rows for those units (24 rows x 384) stay in SMEM across all steps.
#define WSTR 388   // padded row stride (conflict-free)

__global__ void __launch_bounds__(256, 1) k_recur(const float* __restrict__ whhf,
                                                  const float* __restrict__ whhb)
{
    extern __shared__ float sm[];
    float* Ws   = sm;                    // 24*388
    float* Hs   = Ws + 24 * WSTR;        // 64*388
    float* Gs   = Hs + 64 * WSTR;        // 64*25
    float* Cs   = Gs + 64 * 25;          // 64*6
    float* Asum = Cs + 64 * 6;           // 64*6

    const int t = threadIdx.x;
    const int cta = blockIdx.x;
    const int dir = cta >> 6;
    const int slice = cta & 63;
    const int u0 = slice * 6;
    const float* whh = dir ? whhb : whhf;
    const float* xgbase = g_xg + (size_t)dir * MROWS * G4;

    // load stationary weights: local row r -> global gate row (r/6)*384 + u0 + r%6
    for (int i = t; i < 24 * HID; i += 256) {
        int r = i / HID, k = i - r * HID;
        int grow = (r / 6) * HID + u0 + (r % 6);
        Ws[r * WSTR + k] = whh[(size_t)grow * HID + k];
    }
    if (t < 64) {
#pragma unroll
        for (int u = 0; u < 6; u++) { Cs[t * 6 + u] = 0.0f; Asum[t * 6 + u] = 0.0f; }
    }
    __syncthreads();

    int nb = 0;
    unsigned int tgt = 0;
    const int n = t >> 2, q = t & 3;

    for (int phase = 0; phase < 2; ++phase) {
        const int T = phase ? LASP : LSEQ;
        for (int s = 0; s < T; ++s) {
            const int tt = dir ? (T - 1 - s) : s;

            // stage full h panel for this dir into SMEM (bypass L1)
            const float4* hsrc = (const float4*)(g_h + ((size_t)(nb * 2 + dir)) * NBATCH * HID);
            for (int j = t; j < (NBATCH * HID) / 4; j += 256) {
                float4 v = __ldcg(hsrc + j);
                int flat = j * 4;
                int nn = flat / HID, kk = flat - nn * HID;
                *(float4*)&Hs[nn * WSTR + kk] = v;
            }
            __syncthreads();

            // thread (n,q): gate q preactivations for 6 units of batch row n
            float acc[6] = {0, 0, 0, 0, 0, 0};
            const float* hrow = &Hs[n * WSTR];
            const float* w0 = &Ws[(q * 6) * WSTR];
#pragma unroll 4
            for (int k = 0; k < HID; k += 4) {
                float4 hv = *(const float4*)(hrow + k);
#pragma unroll
                for (int u = 0; u < 6; u++) {
                    float4 wv = *(const float4*)(w0 + u * WSTR + k);
                    acc[u] = fmaf(hv.x, wv.x, acc[u]);
                    acc[u] = fmaf(hv.y, wv.y, acc[u]);
                    acc[u] = fmaf(hv.z, wv.z, acc[u]);
                    acc[u] = fmaf(hv.w, wv.w, acc[u]);
                }
            }
            size_t row = phase ? (size_t)(SROWS + n * LASP + tt) : (size_t)(n * LSEQ + tt);
            const float* xr = xgbase + row * G4 + q * HID + u0;
#pragma unroll
            for (int u = 0; u < 6; u++) Gs[n * 25 + q * 6 + u] = acc[u] + xr[u];
            __syncthreads();

            // combine gates, update c/h, publish h
            if (t < 64) {
                int n2 = t;
                float* hout = g_h + ((size_t)(((nb ^ 1) * 2 + dir)) * NBATCH * HID) + n2 * HID + u0;
#pragma unroll
                for (int u = 0; u < 6; u++) {
                    float gi = Gs[n2 * 25 + u];
                    float gf = Gs[n2 * 25 + 6 + u];
                    float gg = Gs[n2 * 25 + 12 + u];
                    float go = Gs[n2 * 25 + 18 + u];
                    float c = sigf(gf) * Cs[n2 * 6 + u] + sigf(gi) * tanhf(gg);
                    float h = sigf(go) * tanhf(c);
                    Cs[n2 * 6 + u] = c;
                    hout[u] = h;
                    if (phase == 0)
                        g_feat[(size_t)(n2 * LSEQ + tt) * DFEAT + dir * HID + u0 + u] = h;
                    else
                        Asum[n2 * 6 + u] += h;
                }
                __threadfence();
            }
            __syncthreads();
            tgt += 128;
            if (t == 0) {
                __threadfence();
                atomicAdd(&g_bar, 1u);
                while (atomicAdd(&g_bar, 0u) < tgt) { }
                __threadfence();
            }
            __syncthreads();
            nb ^= 1;
        }
        if (phase == 0) {
            // reset h (own region) and c before aspect sequence
            if (t < 64) {
                float* hout = g_h + ((size_t)(nb * 2 + dir)) * NBATCH * HID + t * HID + u0;
#pragma unroll
                for (int u = 0; u < 6; u++) { hout[u] = 0.0f; Cs[t * 6 + u] = 0.0f; }
                __threadfence();
            }
            __syncthreads();
            tgt += 128;
            if (t == 0) {
                __threadfence();
                atomicAdd(&g_bar, 1u);
                while (atomicAdd(&g_bar, 0u) < tgt) { }
                __threadfence();
            }
            __syncthreads();
        }
    }
    if (t < 64) {
#pragma unroll
        for (int u = 0; u < 6; u++)
            g_aspv[t * DFEAT + dir * HID + u0 + u] = Asum[t * 6 + u] * (1.0f / LASP);
    }
}

// ---------------- attention: dots ----------------
__global__ void k_dots()
{
    __shared__ float As[DFEAT];
    int n = blockIdx.x;
    for (int i = threadIdx.x; i < DFEAT; i += 256) As[i] = g_aspv[n * DFEAT + i];
    __syncthreads();
    int warp = threadIdx.x >> 5, lane = threadIdx.x & 31;
    int l = blockIdx.y * 8 + warp;
    const float* f = g_feat + (size_t)(n * LSEQ + l) * DFEAT;
    float s = 0.0f;
    for (int i = lane * 4; i < DFEAT; i += 128) {
        float4 fv = *(const float4*)(f + i);
        float4 av = *(const float4*)(&As[i]);
        s += fv.x * av.x + fv.y * av.y + fv.z * av.z + fv.w * av.w;
    }
#pragma unroll
    for (int o = 16; o; o >>= 1) s += __shfl_xor_sync(0xFFFFFFFFu, s, o);
    if (lane == 0) g_dot[n * LSEQ + l] = s;
}

// ---------------- masked softmax over L ----------------
__global__ void k_softmax(const int* __restrict__ tl)
{
    __shared__ float redm[8];
    __shared__ float reds[8];
    int n = blockIdx.x, t = threadIdx.x;
    int len = tl[n];
    float d = g_dot[n * LSEQ + t];
    float v = (t < len) ? d : -1e30f;
    float m = v;
#pragma unroll
    for (int o = 16; o; o >>= 1) m = fmaxf(m, __shfl_xor_sync(0xFFFFFFFFu, m, o));
    if ((t & 31) == 0) redm[t >> 5] = m;
    __syncthreads();
    if (t == 0) {
        float x = redm[0];
        for (int i = 1; i < 8; i++) x = fmaxf(x, redm[i]);
        redm[0] = x;
    }
    __syncthreads();
    m = redm[0];
    float e = __expf(v - m);
    float ssum = e;
#pragma unroll
    for (int o = 16; o; o >>= 1) ssum += __shfl_xor_sync(0xFFFFFFFFu, ssum, o);
    if ((t & 31) == 0) reds[t >> 5] = ssum;
    __syncthreads();
    if (t == 0) {
        float x = 0.0f;
        for (int i = 0; i < 8; i++) x += reds[i];
        reds[0] = x;
    }
    __syncthreads();
    g_att[n * LSEQ + t] = e / reds[0];
}

// ---------------- pooled = sum_l feat*att / 6 ----------------
__global__ void k_pool()
{
    __shared__ float at[LSEQ];
    int n = blockIdx.x, t = threadIdx.x;
    at[t] = g_att[n * LSEQ + t];
    __syncthreads();
    for (int d = t; d < DFEAT; d += 256) {
        float s = 0.0f;
        const float* f = g_feat + (size_t)n * LSEQ * DFEAT + d;
#pragma unroll 4
        for (int l = 0; l < LSEQ; l++) s += f[(size_t)l * DFEAT] * at[l];
        g_pool[n * DFEAT + d] = s * (1.0f / 6.0f);
    }
}

// ---------------- broadcast outputs ----------------
__global__ void k_out(float* __restrict__ out)
{
    const size_t n_logit = (size_t)NBATCH * LSEQ * NCLS;
    const size_t total = n_logit + (size_t)NBATCH * LSEQ * DFEAT;
    size_t i = (size_t)blockIdx.x * blockDim.x + threadIdx.x;
    size_t stride = (size_t)gridDim.x * blockDim.x;
    for (; i < total; i += stride) {
        if (i < n_logit) {
            size_t nl = i / NCLS; int c = (int)(i - nl * NCLS);
            int n = (int)(nl / LSEQ);
            out[i] = g_logits[n * NCLS + c];
        } else {
            size_t j = i - n_logit;
            size_t nl = j / DFEAT; int d = (int)(j - nl * DFEAT);
            int n = (int)(nl / LSEQ);
            out[i] = g_pool[n * DFEAT + d];
        }
    }
}

// ---------------- host launch ----------------
extern "C" void kernel_launch(void* const* d_in, const int* in_sizes, int n_in,
                              void* d_out, int out_size)
{
    const int*   sentence = (const int*)d_in[0];
    const int*   aspect   = (const int*)d_in[1];
    const int*   text_len = (const int*)d_in[2];
    const float* emb      = (const float*)d_in[3];
    const float* wih_f    = (const float*)d_in[4];
    const float* whh_f    = (const float*)d_in[5];
    const float* bih_f    = (const float*)d_in[6];
    const float* bhh_f    = (const float*)d_in[7];
    const float* wih_b    = (const float*)d_in[8];
    const float* whh_b    = (const float*)d_in[9];
    const float* bih_b    = (const float*)d_in[10];
    const float* bhh_b    = (const float*)d_in[11];
    const float* b1       = (const float*)d_in[13];
    const float* b2       = (const float*)d_in[15];
    const float* bf       = (const float*)d_in[17];
    float* out = (float*)d_out;

    // resolve device-symbol addresses (host API, no allocation, capture-safe)
    float *pX, *pxg, *pWt, *pBias, *pW1t, *pW2t, *pWft, *pPool, *pX1, *pX2, *pLogits;
    cudaGetSymbolAddress((void**)&pX, g_X);
    cudaGetSymbolAddress((void**)&pxg, g_xg);
    cudaGetSymbolAddress((void**)&pWt, g_Wt);
    cudaGetSymbolAddress((void**)&pBias, g_bias);
    cudaGetSymbolAddress((void**)&pW1t, g_W1t);
    cudaGetSymbolAddress((void**)&pW2t, g_W2t);
    cudaGetSymbolAddress((void**)&pWft, g_Wft);
    cudaGetSymbolAddress((void**)&pPool, g_pool);
    cudaGetSymbolAddress((void**)&pX1, g_x1);
    cudaGetSymbolAddress((void**)&pX2, g_x2);
    cudaGetSymbolAddress((void**)&pLogits, g_logits);

    static int smem_set = 0;
    int recur_smem = (24 * WSTR + 64 * WSTR + 64 * 25 + 64 * 6 + 64 * 6) * 4;
    if (!smem_set) {
        cudaFuncSetAttribute(k_recur, cudaFuncAttributeMaxDynamicSharedMemorySize, recur_smem);
        smem_set = 1;
    }

    k_prep<<<512, 256>>>(wih_f, wih_b, bih_f, bhh_f, bih_b, bhh_b,
                         (const float*)d_in[12], (const float*)d_in[14], (const float*)d_in[16]);
    k_gather<<<2048, 256>>>(sentence, aspect, emb);

    dim3 ggrid(MROWS / BM, G4 / BN);
    k_gemm<<<ggrid, 256>>>(pX, KP, pWt, G4, pBias, pxg, G4, MROWS, G4, KP, 0);
    k_gemm<<<ggrid, 256>>>(pX, KP, pWt + (size_t)KP * G4, G4, pBias + G4,
                           pxg + (size_t)MROWS * G4, G4, MROWS, G4, KP, 0);

    k_recur<<<128, 256, recur_smem>>>(whh_f, whh_b);

    k_dots<<<dim3(NBATCH, LSEQ / 8), 256>>>();
    k_softmax<<<NBATCH, 256>>>(text_len);
    k_pool<<<NBATCH, 256>>>();

    k_gemm<<<dim3(1, FIN / BN), 256>>>(pPool, DFEAT, pW1t, FIN, b1, pX1, FIN, NBATCH, FIN, DFEAT, 1);
    k_gemm<<<dim3(1, FIN / BN), 256>>>(pX1, FIN, pW2t, FIN, b2, pX2, FIN, NBATCH, FIN, FIN, 1);
    k_gemm<<<dim3(1, 1), 256>>>(pX2, FIN, pWft, 64, bf, pLogits, NCLS, NBATCH, NCLS, FIN, 0);

    k_out<<<4096, 256>>>(out);
}

// round 6
// speedup vs baseline: 1.4005x; 1.4005x over previous
#include <cuda_runtime.h>
#include <cuda_bf16.h>
#include <cstddef>
#include <cstdint>

#define NBATCH 64
#define LSEQ   256
#define LASP   8
#define EMB    300
#define KP     320
#define HID    384
#define G4     1536
#define DFEAT  768
#define FIN    768
#define NCLS   3
#define SROWS  (NBATCH*LSEQ)
#define AROWS  (NBATCH*LASP)
#define MROWS  (SROWS+AROWS)

// ---------------- device scratch (static; no runtime allocation) ----------------
__device__ float g_X[MROWS * KP];
__device__ float g_xg[2 * MROWS * G4];
__device__ float g_Wt[2 * KP * G4];
__device__ float g_bias[2 * G4];
__device__ float g_W1t[FIN * FIN];
__device__ float g_W2t[FIN * FIN];
__device__ float g_Wft[FIN * 128];
__device__ float g_feat[(size_t)SROWS * DFEAT];
__device__ float g_h[2 * 2 * NBATCH * HID];
__device__ float g_aspv[NBATCH * DFEAT];
__device__ float g_dot[NBATCH * LSEQ];
__device__ float g_att[NBATCH * LSEQ];
__device__ float g_pool[NBATCH * DFEAT];
__device__ float g_x1[NBATCH * FIN];
__device__ float g_x2[NBATCH * FIN];
__device__ float g_logits[NBATCH * NCLS];
__device__ unsigned int g_bar;

__device__ __forceinline__ float sigf(float x) { return 1.0f / (1.0f + __expf(-x)); }

// cp.async helpers
__device__ __forceinline__ void cp_async16(uint32_t dst, const void* src) {
    asm volatile("cp.async.cg.shared.global [%0], [%1], 16;\n" :: "r"(dst), "l"(src));
}
__device__ __forceinline__ void cp_commit() { asm volatile("cp.async.commit_group;\n" ::: "memory"); }
template<int N> __device__ __forceinline__ void cp_wait() {
    asm volatile("cp.async.wait_group %0;\n" :: "n"(N) : "memory");
}

// ---------------- prep: weight transposes, bias sums, barrier reset ----------------
__global__ void k_prep(const float* __restrict__ wih_f, const float* __restrict__ wih_b,
                       const float* __restrict__ bih_f, const float* __restrict__ bhh_f,
                       const float* __restrict__ bih_b, const float* __restrict__ bhh_b,
                       const float* __restrict__ W1, const float* __restrict__ W2,
                       const float* __restrict__ Wf)
{
    int tid = blockIdx.x * blockDim.x + threadIdx.x;
    int stride = gridDim.x * blockDim.x;
    for (int i = tid; i < 2 * KP * G4; i += stride) {
        int d = i / (KP * G4);
        int r = i - d * (KP * G4);
        int k = r / G4, g = r - (r / G4) * G4;
        const float* w = d ? wih_b : wih_f;
        g_Wt[i] = (k < EMB) ? w[g * EMB + k] : 0.0f;
    }
    for (int i = tid; i < 2 * G4; i += stride) {
        int d = i / G4, g = i - d * G4;
        g_bias[i] = d ? (bih_b[g] + bhh_b[g]) : (bih_f[g] + bhh_f[g]);
    }
    for (int i = tid; i < FIN * FIN; i += stride) {
        int k = i / FIN, n = i - (i / FIN) * FIN;
        g_W1t[i] = W1[n * FIN + k];
        g_W2t[i] = W2[n * FIN + k];
    }
    for (int i = tid; i < FIN * 128; i += stride) {
        int k = i / 128, c = i - (i / 128) * 128;
        g_Wft[i] = (c < NCLS) ? Wf[c * FIN + k] : 0.0f;
    }
    if (tid == 0) g_bar = 0u;
}

// ---------------- gather embeddings (padded) + zero h state ----------------
__global__ void k_gather(const int* __restrict__ sentence, const int* __restrict__ aspect,
                         const float* __restrict__ emb)
{
    int tid = blockIdx.x * blockDim.x + threadIdx.x;
    int stride = gridDim.x * blockDim.x;
    for (int i = tid; i < MROWS * KP; i += stride) {
        int row = i / KP, k = i - row * KP;
        int tok = (row < SROWS) ? sentence[row] : aspect[row - SROWS];
        g_X[i] = (k < EMB) ? emb[(size_t)tok * EMB + k] : 0.0f;
    }
    for (int i = tid; i < 2 * 2 * NBATCH * HID; i += stride) g_h[i] = 0.0f;
}

// ---------------- fp32 GEMM 128x128x16: C = [relu](A[M,K] @ Bt[K,N] + bias) ----------------
#define BM 128
#define BN 128
#define BK 16

__global__ void __launch_bounds__(256) k_gemm(
    const float* __restrict__ A, int lda,
    const float* __restrict__ Bt, int ldb,
    const float* __restrict__ bias,
    float* __restrict__ C, int ldc,
    int M, int Nn, int K, int relu)
{
    __shared__ float As[BK][BM + 4];
    __shared__ float Bs[BK][BN + 4];
    int t = threadIdx.x;
    int tx = t & 15, ty = t >> 4;
    int m0 = blockIdx.x * BM, n0 = blockIdx.y * BN;
    float acc[8][8];
#pragma unroll
    for (int i = 0; i < 8; i++)
#pragma unroll
        for (int j = 0; j < 8; j++) acc[i][j] = 0.0f;

    int nkt = K / BK;
    for (int kt = 0; kt < nkt; ++kt) {
        int k0 = kt * BK;
        float4 av[2], bv[2];
#pragma unroll
        for (int q = 0; q < 2; q++) {
            int f = t + 256 * q;
            int row = f >> 2, kq = (f & 3) * 4;
            int gm = m0 + row;
            av[q] = (gm < M) ? *(const float4*)(A + (size_t)gm * lda + k0 + kq)
                             : make_float4(0.f, 0.f, 0.f, 0.f);
        }
#pragma unroll
        for (int q = 0; q < 2; q++) {
            int f = t + 256 * q;
            int kk = f >> 5, nq = (f & 31) * 4;
            bv[q] = *(const float4*)(Bt + (size_t)(k0 + kk) * ldb + n0 + nq);
        }
        __syncthreads();
#pragma unroll
        for (int q = 0; q < 2; q++) {
            int f = t + 256 * q;
            int row = f >> 2, kq = (f & 3) * 4;
            As[kq + 0][row] = av[q].x; As[kq + 1][row] = av[q].y;
            As[kq + 2][row] = av[q].z; As[kq + 3][row] = av[q].w;
        }
#pragma unroll
        for (int q = 0; q < 2; q++) {
            int f = t + 256 * q;
            int kk = f >> 5, nq = (f & 31) * 4;
            *(float4*)&Bs[kk][nq] = bv[q];
        }
        __syncthreads();
#pragma unroll
        for (int k = 0; k < BK; k++) {
            float4 b0 = *(float4*)&Bs[k][tx * 4];
            float4 b1 = *(float4*)&Bs[k][tx * 4 + 64];
            float4 a0 = *(float4*)&As[k][ty * 8];
            float4 a1 = *(float4*)&As[k][ty * 8 + 4];
            float a[8] = {a0.x, a0.y, a0.z, a0.w, a1.x, a1.y, a1.z, a1.w};
            float b[8] = {b0.x, b0.y, b0.z, b0.w, b1.x, b1.y, b1.z, b1.w};
#pragma unroll
            for (int i = 0; i < 8; i++)
#pragma unroll
                for (int j = 0; j < 8; j++)
                    acc[i][j] = fmaf(a[i], b[j], acc[i][j]);
        }
        __syncthreads();
    }
#pragma unroll
    for (int i = 0; i < 8; i++) {
        int gm = m0 + ty * 8 + i;
        if (gm < M) {
#pragma unroll
            for (int j = 0; j < 8; j++) {
                int gn = n0 + tx * 4 + (j < 4 ? j : 64 + j - 4);
                if (gn < Nn) {
                    float v = acc[i][j];
                    if (bias) v += bias[gn];
                    if (relu) v = fmaxf(v, 0.0f);
                    C[(size_t)gm * ldc + gn] = v;
                }
            }
        }
    }
}

// ---------------- persistent BiLSTM recurrence ----------------
// 128 CTAs: cta = dir*64 + slice; slice owns hidden units [slice*6, slice*6+6).
// Thread t: kt = t&3 (k-slice), rt = (t>>2)&3 (gate), ntid = t>>4 (4 batch rows).
// Per thread: acc[4 rows][6 units]; k-partials reduced via shfl over kt lanes.
#define HSTR 388   // h panel row stride (floats)
#define WSTR 400   // weight row stride (400 % 32 == 16 -> conflict-free pairs)

__global__ void __launch_bounds__(256, 1) k_recur(const float* __restrict__ whhf,
                                                  const float* __restrict__ whhb)
{
    extern __shared__ float sm[];
    float* Ws   = sm;                    // 24*400
    float* Hs   = Ws + 24 * WSTR;        // 64*388
    float* Gs   = Hs + 64 * HSTR;        // 64*25  (h@W sums, gate-major)
    float* Xs   = Gs + 64 * 25;          // 64*25  (xg staged)
    float* Cs   = Xs + 64 * 25;          // 64*6
    float* Asum = Cs + 64 * 6;           // 64*6

    const int t = threadIdx.x;
    const int cta = blockIdx.x;
    const int dir = cta >> 6;
    const int slice = cta & 63;
    const int u0 = slice * 6;
    const float* whh = dir ? whhb : whhf;
    const float* xgbase = g_xg + (size_t)dir * MROWS * G4;

    const int kt = t & 3, rt = (t >> 2) & 3, ntid = t >> 4;
    const int n0 = ntid * 4;

    // stationary weights: Ws row lr = j*4 + rt holds whh row (gate=lr&3, unit=u0+lr>>2)
    for (int i = t; i < 24 * HID; i += 256) {
        int lr = i / HID, k = i - lr * HID;
        int gate = lr & 3, u = lr >> 2;
        Ws[lr * WSTR + k] = whh[(size_t)(gate * HID + u0 + u) * HID + k];
    }
    if (t < 64) {
#pragma unroll
        for (int u = 0; u < 6; u++) { Cs[t * 6 + u] = 0.0f; Asum[t * 6 + u] = 0.0f; }
    }
    __syncthreads();

    // precomputed staging assignment (6 float4 per thread per chunk)
    int srows[6], scols[6];
    uint32_t sdst[6];
    uint32_t HsU = (uint32_t)__cvta_generic_to_shared(Hs);
#pragma unroll
    for (int p = 0; p < 6; p++) {
        int idx = t + 256 * p;          // 0..1535
        srows[p] = idx / 24;
        scols[p] = idx - srows[p] * 24; // float4 within chunk row
        sdst[p] = HsU + (uint32_t)(srows[p] * HSTR + scols[p] * 4) * 4u;
    }
    const int xn = t >> 2, xgate = t & 3;

    int nb = 0;
    unsigned int tgt = 0;

    for (int phase = 0; phase < 2; ++phase) {
        const int T = phase ? LASP : LSEQ;
        for (int s = 0; s < T; ++s) {
            const int tt = dir ? (T - 1 - s) : s;

            // ---- issue async h staging (4 chunks of 96 floats/row) ----
            const float* hsrc = g_h + ((size_t)(nb * 2 + dir)) * NBATCH * HID;
#pragma unroll
            for (int c = 0; c < 4; c++) {
#pragma unroll
                for (int p = 0; p < 6; p++) {
                    const float* src = hsrc + srows[p] * HID + (c * 24 + scols[p]) * 4;
                    cp_async16(sdst[p] + (uint32_t)(c * 24 * 16), src);
                }
                cp_commit();
            }

            // ---- stage xg gate biases while TMA^H cp.async flies ----
            {
                size_t row = phase ? (size_t)(SROWS + xn * LASP + tt) : (size_t)(xn * LSEQ + tt);
                const float* xp = xgbase + row * G4 + xgate * HID + u0;
#pragma unroll
                for (int j = 0; j < 6; j++) Xs[xn * 25 + xgate * 6 + j] = xp[j];
            }

            // ---- compute h @ W^T, chunked/pipelined ----
            float acc[4][6];
#pragma unroll
            for (int i = 0; i < 4; i++)
#pragma unroll
                for (int j = 0; j < 6; j++) acc[i][j] = 0.0f;

#pragma unroll
            for (int c = 0; c < 4; c++) {
                if (c == 0) cp_wait<3>();
                else if (c == 1) cp_wait<2>();
                else if (c == 2) cp_wait<1>();
                else cp_wait<0>();
                __syncthreads();
#pragma unroll
                for (int it2 = 0; it2 < 6; it2++) {
                    int fk = (c * 24 + it2 * 4 + kt) * 4;   // float column
                    float4 hv[4], wv[6];
#pragma unroll
                    for (int i = 0; i < 4; i++)
                        hv[i] = *(const float4*)&Hs[(n0 + i) * HSTR + fk];
#pragma unroll
                    for (int j = 0; j < 6; j++)
                        wv[j] = *(const float4*)&Ws[(j * 4 + rt) * WSTR + fk];
#pragma unroll
                    for (int i = 0; i < 4; i++)
#pragma unroll
                        for (int j = 0; j < 6; j++) {
                            acc[i][j] = fmaf(hv[i].x, wv[j].x, acc[i][j]);
                            acc[i][j] = fmaf(hv[i].y, wv[j].y, acc[i][j]);
                            acc[i][j] = fmaf(hv[i].z, wv[j].z, acc[i][j]);
                            acc[i][j] = fmaf(hv[i].w, wv[j].w, acc[i][j]);
                        }
                }
            }

            // ---- reduce k-partials across kt lanes (bits 0-1) ----
#pragma unroll
            for (int i = 0; i < 4; i++)
#pragma unroll
                for (int j = 0; j < 6; j++) {
                    float v = acc[i][j];
                    v += __shfl_xor_sync(0xFFFFFFFFu, v, 1);
                    v += __shfl_xor_sync(0xFFFFFFFFu, v, 2);
                    acc[i][j] = v;
                }
            if (kt == 0) {
#pragma unroll
                for (int i = 0; i < 4; i++)
#pragma unroll
                    for (int j = 0; j < 6; j++)
                        Gs[(n0 + i) * 25 + rt * 6 + j] = acc[i][j];
            }
            __syncthreads();

            // ---- combine gates, update c/h, publish h ----
            if (t < 64) {
                int n2 = t;
                float* hout = g_h + ((size_t)(((nb ^ 1) * 2 + dir)) * NBATCH * HID) + n2 * HID + u0;
#pragma unroll
                for (int u = 0; u < 6; u++) {
                    float gi = Gs[n2 * 25 + u]      + Xs[n2 * 25 + u];
                    float gf = Gs[n2 * 25 + 6 + u]  + Xs[n2 * 25 + 6 + u];
                    float gg = Gs[n2 * 25 + 12 + u] + Xs[n2 * 25 + 12 + u];
                    float go = Gs[n2 * 25 + 18 + u] + Xs[n2 * 25 + 18 + u];
                    float c = sigf(gf) * Cs[n2 * 6 + u] + sigf(gi) * tanhf(gg);
                    float h = sigf(go) * tanhf(c);
                    Cs[n2 * 6 + u] = c;
                    hout[u] = h;
                    if (phase == 0)
                        g_feat[(size_t)(n2 * LSEQ + tt) * DFEAT + dir * HID + u0 + u] = h;
                    else
                        Asum[n2 * 6 + u] += h;
                }
                __threadfence();
            }
            __syncthreads();
            tgt += 128;
            if (t == 0) {
                __threadfence();
                atomicAdd(&g_bar, 1u);
                while (atomicAdd(&g_bar, 0u) < tgt) { }
                __threadfence();
            }
            __syncthreads();
            nb ^= 1;
        }
        if (phase == 0) {
            // reset h (own region, buffer to be read next) and c before aspect pass
            if (t < 64) {
                float* hout = g_h + ((size_t)(nb * 2 + dir)) * NBATCH * HID + t * HID + u0;
#pragma unroll
                for (int u = 0; u < 6; u++) { hout[u] = 0.0f; Cs[t * 6 + u] = 0.0f; }
                __threadfence();
            }
            __syncthreads();
            tgt += 128;
            if (t == 0) {
                __threadfence();
                atomicAdd(&g_bar, 1u);
                while (atomicAdd(&g_bar, 0u) < tgt) { }
                __threadfence();
            }
            __syncthreads();
        }
    }
    if (t < 64) {
#pragma unroll
        for (int u = 0; u < 6; u++)
            g_aspv[t * DFEAT + dir * HID + u0 + u] = Asum[t * 6 + u] * (1.0f / LASP);
    }
}

// ---------------- attention: dots ----------------
__global__ void k_dots()
{
    __shared__ float As2[DFEAT];
    int n = blockIdx.x;
    for (int i = threadIdx.x; i < DFEAT; i += 256) As2[i] = g_aspv[n * DFEAT + i];
    __syncthreads();
    int warp = threadIdx.x >> 5, lane = threadIdx.x & 31;
    int l = blockIdx.y * 8 + warp;
    const float* f = g_feat + (size_t)(n * LSEQ + l) * DFEAT;
    float s = 0.0f;
    for (int i = lane * 4; i < DFEAT; i += 128) {
        float4 fv = *(const float4*)(f + i);
        float4 av = *(const float4*)(&As2[i]);
        s += fv.x * av.x + fv.y * av.y + fv.z * av.z + fv.w * av.w;
    }
#pragma unroll
    for (int o = 16; o; o >>= 1) s += __shfl_xor_sync(0xFFFFFFFFu, s, o);
    if (lane == 0) g_dot[n * LSEQ + l] = s;
}

// ---------------- masked softmax over L ----------------
__global__ void k_softmax(const int* __restrict__ tl)
{
    __shared__ float redm[8];
    __shared__ float reds[8];
    int n = blockIdx.x, t = threadIdx.x;
    int len = tl[n];
    float d = g_dot[n * LSEQ + t];
    float v = (t < len) ? d : -1e30f;
    float m = v;
#pragma unroll
    for (int o = 16; o; o >>= 1) m = fmaxf(m, __shfl_xor_sync(0xFFFFFFFFu, m, o));
    if ((t & 31) == 0) redm[t >> 5] = m;
    __syncthreads();
    if (t == 0) {
        float x = redm[0];
        for (int i = 1; i < 8; i++) x = fmaxf(x, redm[i]);
        redm[0] = x;
    }
    __syncthreads();
    m = redm[0];
    float e = __expf(v - m);
    float ssum = e;
#pragma unroll
    for (int o = 16; o; o >>= 1) ssum += __shfl_xor_sync(0xFFFFFFFFu, ssum, o);
    if ((t & 31) == 0) reds[t >> 5] = ssum;
    __syncthreads();
    if (t == 0) {
        float x = 0.0f;
        for (int i = 0; i < 8; i++) x += reds[i];
        reds[0] = x;
    }
    __syncthreads();
    g_att[n * LSEQ + t] = e / reds[0];
}

// ---------------- pooled = sum_l feat*att / 6 ----------------
__global__ void k_pool()
{
    __shared__ float at[LSEQ];
    int n = blockIdx.x, t = threadIdx.x;
    at[t] = g_att[n * LSEQ + t];
    __syncthreads();
    for (int d = t; d < DFEAT; d += 256) {
        float s = 0.0f;
        const float* f = g_feat + (size_t)n * LSEQ * DFEAT + d;
#pragma unroll 4
        for (int l = 0; l < LSEQ; l++) s += f[(size_t)l * DFEAT] * at[l];
        g_pool[n * DFEAT + d] = s * (1.0f / 6.0f);
    }
}

// ---------------- broadcast outputs ----------------
__global__ void k_out(float* __restrict__ out)
{
    const size_t n_logit = (size_t)NBATCH * LSEQ * NCLS;
    const size_t total = n_logit + (size_t)NBATCH * LSEQ * DFEAT;
    size_t i = (size_t)blockIdx.x * blockDim.x + threadIdx.x;
    size_t stride = (size_t)gridDim.x * blockDim.x;
    for (; i < total; i += stride) {
        if (i < n_logit) {
            size_t nl = i / NCLS; int c = (int)(i - nl * NCLS);
            int n = (int)(nl / LSEQ);
            out[i] = g_logits[n * NCLS + c];
        } else {
            size_t j = i - n_logit;
            size_t nl = j / DFEAT; int d = (int)(j - nl * DFEAT);
            int n = (int)(nl / LSEQ);
            out[i] = g_pool[n * DFEAT + d];
        }
    }
}

// ---------------- host launch ----------------
extern "C" void kernel_launch(void* const* d_in, const int* in_sizes, int n_in,
                              void* d_out, int out_size)
{
    const int*   sentence = (const int*)d_in[0];
    const int*   aspect   = (const int*)d_in[1];
    const int*   text_len = (const int*)d_in[2];
    const float* emb      = (const float*)d_in[3];
    const float* wih_f    = (const float*)d_in[4];
    const float* whh_f    = (const float*)d_in[5];
    const float* bih_f    = (const float*)d_in[6];
    const float* bhh_f    = (const float*)d_in[7];
    const float* wih_b    = (const float*)d_in[8];
    const float* whh_b    = (const float*)d_in[9];
    const float* bih_b    = (const float*)d_in[10];
    const float* bhh_b    = (const float*)d_in[11];
    const float* b1       = (const float*)d_in[13];
    const float* b2       = (const float*)d_in[15];
    const float* bf       = (const float*)d_in[17];
    float* out = (float*)d_out;

    float *pX, *pxg, *pWt, *pBias, *pW1t, *pW2t, *pWft, *pPool, *pX1, *pX2, *pLogits;
    cudaGetSymbolAddress((void**)&pX, g_X);
    cudaGetSymbolAddress((void**)&pxg, g_xg);
    cudaGetSymbolAddress((void**)&pWt, g_Wt);
    cudaGetSymbolAddress((void**)&pBias, g_bias);
    cudaGetSymbolAddress((void**)&pW1t, g_W1t);
    cudaGetSymbolAddress((void**)&pW2t, g_W2t);
    cudaGetSymbolAddress((void**)&pWft, g_Wft);
    cudaGetSymbolAddress((void**)&pPool, g_pool);
    cudaGetSymbolAddress((void**)&pX1, g_x1);
    cudaGetSymbolAddress((void**)&pX2, g_x2);
    cudaGetSymbolAddress((void**)&pLogits, g_logits);

    static int smem_set = 0;
    int recur_smem = (24 * WSTR + 64 * HSTR + 64 * 25 + 64 * 25 + 64 * 6 + 64 * 6) * 4;
    if (!smem_set) {
        cudaFuncSetAttribute(k_recur, cudaFuncAttributeMaxDynamicSharedMemorySize, recur_smem);
        smem_set = 1;
    }

    k_prep<<<512, 256>>>(wih_f, wih_b, bih_f, bhh_f, bih_b, bhh_b,
                         (const float*)d_in[12], (const float*)d_in[14], (const float*)d_in[16]);
    k_gather<<<2048, 256>>>(sentence, aspect, emb);

    dim3 ggrid(MROWS / BM, G4 / BN);
    k_gemm<<<ggrid, 256>>>(pX, KP, pWt, G4, pBias, pxg, G4, MROWS, G4, KP, 0);
    k_gemm<<<ggrid, 256>>>(pX, KP, pWt + (size_t)KP * G4, G4, pBias + G4,
                           pxg + (size_t)MROWS * G4, G4, MROWS, G4, KP, 0);

    k_recur<<<128, 256, recur_smem>>>(whh_f, whh_b);

    k_dots<<<dim3(NBATCH, LSEQ / 8), 256>>>();
    k_softmax<<<NBATCH, 256>>>(text_len);
    k_pool<<<NBATCH, 256>>>();

    k_gemm<<<dim3(1, FIN / BN), 256>>>(pPool, DFEAT, pW1t, FIN, b1, pX1, FIN, NBATCH, FIN, DFEAT, 1);
    k_gemm<<<dim3(1, FIN / BN), 256>>>(pX1, FIN, pW2t, FIN, b2, pX2, FIN, NBATCH, FIN, FIN, 1);
    k_gemm<<<dim3(1, 1), 256>>>(pX2, FIN, pWft, 128, bf, pLogits, NCLS, NBATCH, NCLS, FIN, 0);

    k_out<<<4096, 256>>>(out);
}

// round 10
// speedup vs baseline: 1.4669x; 1.0474x over previous
#include <cuda_runtime.h>
#include <cuda_bf16.h>
#include <cstddef>
#include <cstdint>

#define NBATCH 64
#define LSEQ   256
#define LASP   8
#define EMB    300
#define KP     320
#define HID    384
#define G4     1536
#define DFEAT  768
#define FIN    768
#define NCLS   3
#define SROWS  (NBATCH*LSEQ)
#define AROWS  (NBATCH*LASP)
#define MROWS  (SROWS+AROWS)

// ---------------- device scratch (static; no runtime allocation) ----------------
__device__ float g_X[MROWS * KP];
__device__ float g_xg[2 * MROWS * G4];
__device__ float g_Wt[2 * KP * G4];
__device__ float g_bias[2 * G4];
__device__ float g_W1t[FIN * FIN];
__device__ float g_W2t[FIN * FIN];
__device__ float g_Wft[FIN * 128];
__device__ float g_feat[(size_t)SROWS * DFEAT];
__device__ float g_h[2 * 2 * NBATCH * HID];
__device__ float g_aspv[NBATCH * DFEAT];
__device__ float g_dot[NBATCH * LSEQ];
__device__ float g_att[NBATCH * LSEQ];
__device__ float g_pool[NBATCH * DFEAT];
__device__ float g_x1[NBATCH * FIN];
__device__ float g_x2[NBATCH * FIN];
__device__ float g_logits[NBATCH * NCLS];
__device__ unsigned int g_bar;

__device__ __forceinline__ float sigf(float x) { return 1.0f / (1.0f + __expf(-x)); }

// packed f32x2 FMA (Blackwell FFMA2 — only reachable via PTX)
__device__ __forceinline__ void fma2(unsigned long long& acc, unsigned long long a,
                                     unsigned long long b) {
    asm("fma.rn.f32x2 %0, %1, %2, %0;" : "+l"(acc) : "l"(a), "l"(b));
}
__device__ __forceinline__ unsigned long long pack2(float lo, float hi) {
    unsigned long long r;
    asm("mov.b64 %0, {%1, %2};" : "=l"(r) : "f"(lo), "f"(hi));
    return r;
}
__device__ __forceinline__ float2 unpack2(unsigned long long v) {
    float2 r;
    asm("mov.b64 {%0, %1}, %2;" : "=f"(r.x), "=f"(r.y) : "l"(v));
    return r;
}

// cp.async helpers
__device__ __forceinline__ void cp_async16(uint32_t dst, const void* src) {
    asm volatile("cp.async.cg.shared.global [%0], [%1], 16;\n" :: "r"(dst), "l"(src));
}
__device__ __forceinline__ void cp_commit() { asm volatile("cp.async.commit_group;\n" ::: "memory"); }
template<int N> __device__ __forceinline__ void cp_wait() {
    asm volatile("cp.async.wait_group %0;\n" :: "n"(N) : "memory");
}

// ---------------- prep: weight transposes, bias sums, barrier reset ----------------
__global__ void k_prep(const float* __restrict__ wih_f, const float* __restrict__ wih_b,
                       const float* __restrict__ bih_f, const float* __restrict__ bhh_f,
                       const float* __restrict__ bih_b, const float* __restrict__ bhh_b,
                       const float* __restrict__ W1, const float* __restrict__ W2,
                       const float* __restrict__ Wf)
{
    int tid = blockIdx.x * blockDim.x + threadIdx.x;
    int stride = gridDim.x * blockDim.x;
    for (int i = tid; i < 2 * KP * G4; i += stride) {
        int d = i / (KP * G4);
        int r = i - d * (KP * G4);
        int k = r / G4, g = r - (r / G4) * G4;
        const float* w = d ? wih_b : wih_f;
        g_Wt[i] = (k < EMB) ? w[g * EMB + k] : 0.0f;
    }
    for (int i = tid; i < 2 * G4; i += stride) {
        int d = i / G4, g = i - d * G4;
        g_bias[i] = d ? (bih_b[g] + bhh_b[g]) : (bih_f[g] + bhh_f[g]);
    }
    for (int i = tid; i < FIN * FIN; i += stride) {
        int k = i / FIN, n = i - (i / FIN) * FIN;
        g_W1t[i] = W1[n * FIN + k];
        g_W2t[i] = W2[n * FIN + k];
    }
    for (int i = tid; i < FIN * 128; i += stride) {
        int k = i / 128, c = i - (i / 128) * 128;
        g_Wft[i] = (c < NCLS) ? Wf[c * FIN + k] : 0.0f;
    }
    if (tid == 0) g_bar = 0u;
}

// ---------------- gather embeddings (padded) + zero h state ----------------
__global__ void k_gather(const int* __restrict__ sentence, const int* __restrict__ aspect,
                         const float* __restrict__ emb)
{
    int tid = blockIdx.x * blockDim.x + threadIdx.x;
    int stride = gridDim.x * blockDim.x;
    for (int i = tid; i < MROWS * KP; i += stride) {
        int row = i / KP, k = i - row * KP;
        int tok = (row < SROWS) ? sentence[row] : aspect[row - SROWS];
        g_X[i] = (k < EMB) ? emb[(size_t)tok * EMB + k] : 0.0f;
    }
    for (int i = tid; i < 2 * 2 * NBATCH * HID; i += stride) g_h[i] = 0.0f;
}

// ---------------- fp32 GEMM 128x128x16, reg-prefetch + FFMA2 ----------------
#define BM 128
#define BN 128
#define BK 16

__global__ void __launch_bounds__(256) k_gemm(
    const float* __restrict__ A, int lda,
    const float* __restrict__ Bt, int ldb,
    const float* __restrict__ bias,
    float* __restrict__ C, int ldc,
    int M, int Nn, int K, int relu)
{
    __shared__ float As[BK][BM + 4];
    __shared__ float Bs[BK][BN + 4];
    int t = threadIdx.x;
    int tx = t & 15, ty = t >> 4;
    int m0 = blockIdx.x * BM, n0 = blockIdx.y * BN;
    unsigned long long acc2[8][4];
#pragma unroll
    for (int i = 0; i < 8; i++)
#pragma unroll
        for (int j = 0; j < 4; j++) acc2[i][j] = 0ull;

    int arow[2], akq[2], bkk[2], bnq[2];
#pragma unroll
    for (int q = 0; q < 2; q++) {
        int f = t + 256 * q;
        arow[q] = f >> 2;  akq[q] = (f & 3) * 4;
        bkk[q]  = f >> 5;  bnq[q] = (f & 31) * 4;
    }

    int nkt = K / BK;
    float4 av[2], bv[2];
    {
#pragma unroll
        for (int q = 0; q < 2; q++) {
            int gm = m0 + arow[q];
            av[q] = (gm < M) ? *(const float4*)(A + (size_t)gm * lda + akq[q])
                             : make_float4(0.f, 0.f, 0.f, 0.f);
            bv[q] = *(const float4*)(Bt + (size_t)bkk[q] * ldb + n0 + bnq[q]);
        }
    }

    for (int kt = 0; kt < nkt; ++kt) {
        __syncthreads();
#pragma unroll
        for (int q = 0; q < 2; q++) {
            As[akq[q] + 0][arow[q]] = av[q].x; As[akq[q] + 1][arow[q]] = av[q].y;
            As[akq[q] + 2][arow[q]] = av[q].z; As[akq[q] + 3][arow[q]] = av[q].w;
            *(float4*)&Bs[bkk[q]][bnq[q]] = bv[q];
        }
        __syncthreads();

        if (kt + 1 < nkt) {
            int k0 = (kt + 1) * BK;
#pragma unroll
            for (int q = 0; q < 2; q++) {
                int gm = m0 + arow[q];
                av[q] = (gm < M) ? *(const float4*)(A + (size_t)gm * lda + k0 + akq[q])
                                 : make_float4(0.f, 0.f, 0.f, 0.f);
                bv[q] = *(const float4*)(Bt + (size_t)(k0 + bkk[q]) * ldb + n0 + bnq[q]);
            }
        }

#pragma unroll
        for (int k = 0; k < BK; k++) {
            ulonglong2 b0 = *(ulonglong2*)&Bs[k][tx * 4];
            ulonglong2 b1 = *(ulonglong2*)&Bs[k][tx * 4 + 64];
            unsigned long long bp[4] = {b0.x, b0.y, b1.x, b1.y};
            float4 a0 = *(float4*)&As[k][ty * 8];
            float4 a1 = *(float4*)&As[k][ty * 8 + 4];
            float a[8] = {a0.x, a0.y, a0.z, a0.w, a1.x, a1.y, a1.z, a1.w};
#pragma unroll
            for (int i = 0; i < 8; i++) {
                unsigned long long as = pack2(a[i], a[i]);
#pragma unroll
                for (int j = 0; j < 4; j++)
                    fma2(acc2[i][j], as, bp[j]);
            }
        }
    }
#pragma unroll
    for (int i = 0; i < 8; i++) {
        int gm = m0 + ty * 8 + i;
        if (gm < M) {
#pragma unroll
            for (int jp = 0; jp < 4; jp++) {
                float2 p = unpack2(acc2[i][jp]);
                int col = tx * 4 + (jp < 2 ? jp * 2 : 64 + (jp - 2) * 2);
#pragma unroll
                for (int e = 0; e < 2; e++) {
                    int gn = n0 + col + e;
                    if (gn < Nn) {
                        float v = e ? p.y : p.x;
                        if (bias) v += bias[gn];
                        if (relu) v = fmaxf(v, 0.0f);
                        C[(size_t)gm * ldc + gn] = v;
                    }
                }
            }
        }
    }
}

// ---------------- persistent BiLSTM recurrence ----------------
#define HSTR 388
#define WSTR 400

__global__ void __launch_bounds__(256, 1) k_recur(const float* __restrict__ whhf,
                                                  const float* __restrict__ whhb)
{
    extern __shared__ float sm[];
    float* Ws   = sm;                    // 24*400
    float* Hs   = Ws + 24 * WSTR;        // 64*388
    float* Gs   = Hs + 64 * HSTR;        // 64*25
    float* Xs   = Gs + 64 * 25;          // 64*25
    float* Cs   = Xs + 64 * 25;          // 64*6
    float* Asum = Cs + 64 * 6;           // 64*6

    const int t = threadIdx.x;
    const int cta = blockIdx.x;
    const int dir = cta >> 6;
    const int slice = cta & 63;
    const int u0 = slice * 6;
    const float* whh = dir ? whhb : whhf;
    const float* xgbase = g_xg + (size_t)dir * MROWS * G4;

    const int kt = t & 3, rt = (t >> 2) & 3, ntid = t >> 4;
    const int n0 = ntid * 4;

    for (int i = t; i < 24 * HID; i += 256) {
        int lr = i / HID, k = i - lr * HID;
        int gate = lr & 3, u = lr >> 2;
        Ws[lr * WSTR + k] = whh[(size_t)(gate * HID + u0 + u) * HID + k];
    }
    if (t < 64) {
#pragma unroll
        for (int u = 0; u < 6; u++) { Cs[t * 6 + u] = 0.0f; Asum[t * 6 + u] = 0.0f; }
    }
    __syncthreads();

    int srows[6], scols[6];
    uint32_t sdst[6];
    uint32_t HsU = (uint32_t)__cvta_generic_to_shared(Hs);
#pragma unroll
    for (int p = 0; p < 6; p++) {
        int idx = t + 256 * p;
        srows[p] = idx / 24;
        scols[p] = idx - srows[p] * 24;
        sdst[p] = HsU + (uint32_t)(srows[p] * HSTR + scols[p] * 4) * 4u;
    }
    const int xn = t >> 2, xgate = t & 3;

    int nb = 0;
    unsigned int tgt = 0;

    for (int phase = 0; phase < 2; ++phase) {
        const int T = phase ? LASP : LSEQ;
        for (int s = 0; s < T; ++s) {
            const int tt = dir ? (T - 1 - s) : s;

            const float* hsrc = g_h + ((size_t)(nb * 2 + dir)) * NBATCH * HID;
#pragma unroll
            for (int c = 0; c < 4; c++) {
#pragma unroll
                for (int p = 0; p < 6; p++) {
                    const float* src = hsrc + srows[p] * HID + (c * 24 + scols[p]) * 4;
                    cp_async16(sdst[p] + (uint32_t)(c * 24 * 16), src);
                }
                cp_commit();
            }

            {
                size_t row = phase ? (size_t)(SROWS + xn * LASP + tt) : (size_t)(xn * LSEQ + tt);
                const float* xp = xgbase + row * G4 + xgate * HID + u0;
#pragma unroll
                for (int j = 0; j < 6; j++) Xs[xn * 25 + xgate * 6 + j] = xp[j];
            }

            unsigned long long acc2[4][6];
#pragma unroll
            for (int i = 0; i < 4; i++)
#pragma unroll
                for (int j = 0; j < 6; j++) acc2[i][j] = 0ull;

#pragma unroll
            for (int c = 0; c < 4; c++) {
                if (c == 0) cp_wait<3>();
                else if (c == 1) cp_wait<2>();
                else if (c == 2) cp_wait<1>();
                else cp_wait<0>();
                __syncthreads();
#pragma unroll
                for (int it2 = 0; it2 < 6; it2++) {
                    int fk = (c * 24 + it2 * 4 + kt) * 4;
                    ulonglong2 hv[4], wv[6];
#pragma unroll
                    for (int i = 0; i < 4; i++)
                        hv[i] = *(const ulonglong2*)&Hs[(n0 + i) * HSTR + fk];
#pragma unroll
                    for (int j = 0; j < 6; j++)
                        wv[j] = *(const ulonglong2*)&Ws[(j * 4 + rt) * WSTR + fk];
#pragma unroll
                    for (int i = 0; i < 4; i++)
#pragma unroll
                        for (int j = 0; j < 6; j++) {
                            fma2(acc2[i][j], hv[i].x, wv[j].x);
                            fma2(acc2[i][j], hv[i].y, wv[j].y);
                        }
                }
            }

#pragma unroll
            for (int i = 0; i < 4; i++)
#pragma unroll
                for (int j = 0; j < 6; j++) {
                    float2 pp = unpack2(acc2[i][j]);
                    float v = pp.x + pp.y;
                    v += __shfl_xor_sync(0xFFFFFFFFu, v, 1);
                    v += __shfl_xor_sync(0xFFFFFFFFu, v, 2);
                    if (kt == 0) Gs[(n0 + i) * 25 + rt * 6 + j] = v;
                }
            __syncthreads();

            if (t < 64) {
                int n2 = t;
                float* hout = g_h + ((size_t)(((nb ^ 1) * 2 + dir)) * NBATCH * HID) + n2 * HID + u0;
#pragma unroll
                for (int u = 0; u < 6; u++) {
                    float gi = Gs[n2 * 25 + u]      + Xs[n2 * 25 + u];
                    float gf = Gs[n2 * 25 + 6 + u]  + Xs[n2 * 25 + 6 + u];
                    float gg = Gs[n2 * 25 + 12 + u] + Xs[n2 * 25 + 12 + u];
                    float go = Gs[n2 * 25 + 18 + u] + Xs[n2 * 25 + 18 + u];
                    float c = sigf(gf) * Cs[n2 * 6 + u] + sigf(gi) * tanhf(gg);
                    float h = sigf(go) * tanhf(c);
                    Cs[n2 * 6 + u] = c;
                    hout[u] = h;
                    if (phase == 0)
                        g_feat[(size_t)(n2 * LSEQ + tt) * DFEAT + dir * HID + u0 + u] = h;
                    else
                        Asum[n2 * 6 + u] += h;
                }
                __threadfence();
            }
            __syncthreads();
            tgt += 128;
            if (t == 0) {
                __threadfence();
                atomicAdd(&g_bar, 1u);
                while (atomicAdd(&g_bar, 0u) < tgt) { }
                __threadfence();
            }
            __syncthreads();
            nb ^= 1;
        }
        if (phase == 0) {
            if (t < 64) {
                float* hout = g_h + ((size_t)(nb * 2 + dir)) * NBATCH * HID + t * HID + u0;
#pragma unroll
                for (int u = 0; u < 6; u++) { hout[u] = 0.0f; Cs[t * 6 + u] = 0.0f; }
                __threadfence();
            }
            __syncthreads();
            tgt += 128;
            if (t == 0) {
                __threadfence();
                atomicAdd(&g_bar, 1u);
                while (atomicAdd(&g_bar, 0u) < tgt) { }
                __threadfence();
            }
            __syncthreads();
        }
    }
    if (t < 64) {
#pragma unroll
        for (int u = 0; u < 6; u++)
            g_aspv[t * DFEAT + dir * HID + u0 + u] = Asum[t * 6 + u] * (1.0f / LASP);
    }
}

// ---------------- attention: dots ----------------
__global__ void k_dots()
{
    __shared__ float As2[DFEAT];
    int n = blockIdx.x;
    for (int i = threadIdx.x; i < DFEAT; i += 256) As2[i] = g_aspv[n * DFEAT + i];
    __syncthreads();
    int warp = threadIdx.x >> 5, lane = threadIdx.x & 31;
    int l = blockIdx.y * 8 + warp;
    const float* f = g_feat + (size_t)(n * LSEQ + l) * DFEAT;
    float s = 0.0f;
    for (int i = lane * 4; i < DFEAT; i += 128) {
        float4 fv = *(const float4*)(f + i);
        float4 av = *(const float4*)(&As2[i]);
        s += fv.x * av.x + fv.y * av.y + fv.z * av.z + fv.w * av.w;
    }
#pragma unroll
    for (int o = 16; o; o >>= 1) s += __shfl_xor_sync(0xFFFFFFFFu, s, o);
    if (lane == 0) g_dot[n * LSEQ + l] = s;
}

// ---------------- masked softmax over L ----------------
__global__ void k_softmax(const int* __restrict__ tl)
{
    __shared__ float redm[8];
    __shared__ float reds[8];
    int n = blockIdx.x, t = threadIdx.x;
    int len = tl[n];
    float d = g_dot[n * LSEQ + t];
    float v = (t < len) ? d : -1e30f;
    float m = v;
#pragma unroll
    for (int o = 16; o; o >>= 1) m = fmaxf(m, __shfl_xor_sync(0xFFFFFFFFu, m, o));
    if ((t & 31) == 0) redm[t >> 5] = m;
    __syncthreads();
    if (t == 0) {
        float x = redm[0];
        for (int i = 1; i < 8; i++) x = fmaxf(x, redm[i]);
        redm[0] = x;
    }
    __syncthreads();
    m = redm[0];
    float e = __expf(v - m);
    float ssum = e;
#pragma unroll
    for (int o = 16; o; o >>= 1) ssum += __shfl_xor_sync(0xFFFFFFFFu, ssum, o);
    if ((t & 31) == 0) reds[t >> 5] = ssum;
    __syncthreads();
    if (t == 0) {
        float x = 0.0f;
        for (int i = 0; i < 8; i++) x += reds[i];
        reds[0] = x;
    }
    __syncthreads();
    g_att[n * LSEQ + t] = e / reds[0];
}

// ---------------- pooled = sum_l feat*att / 6 ----------------
__global__ void k_pool()
{
    __shared__ float at[LSEQ];
    int n = blockIdx.x, t = threadIdx.x;
    at[t] = g_att[n * LSEQ + t];
    __syncthreads();
    for (int d = t; d < DFEAT; d += 256) {
        float s = 0.0f;
        const float* f = g_feat + (size_t)n * LSEQ * DFEAT + d;
#pragma unroll 4
        for (int l = 0; l < LSEQ; l++) s += f[(size_t)l * DFEAT] * at[l];
        g_pool[n * DFEAT + d] = s * (1.0f / 6.0f);
    }
}

// ---------------- broadcast outputs ----------------
__global__ void k_out(float* __restrict__ out)
{
    const size_t n_logit = (size_t)NBATCH * LSEQ * NCLS;
    const size_t total = n_logit + (size_t)NBATCH * LSEQ * DFEAT;
    size_t i = (size_t)blockIdx.x * blockDim.x + threadIdx.x;
    size_t stride = (size_t)gridDim.x * blockDim.x;
    for (; i < total; i += stride) {
        if (i < n_logit) {
            size_t nl = i / NCLS; int c = (int)(i - nl * NCLS);
            int n = (int)(nl / LSEQ);
            out[i] = g_logits[n * NCLS + c];
        } else {
            size_t j = i - n_logit;
            size_t nl = j / DFEAT; int d = (int)(j - nl * DFEAT);
            int n = (int)(nl / LSEQ);
            out[i] = g_pool[n * DFEAT + d];
        }
    }
}

// ---------------- host launch ----------------
extern "C" void kernel_launch(void* const* d_in, const int* in_sizes, int n_in,
                              void* d_out, int out_size)
{
    const int*   sentence = (const int*)d_in[0];
    const int*   aspect   = (const int*)d_in[1];
    const int*   text_len = (const int*)d_in[2];
    const float* emb      = (const float*)d_in[3];
    const float* wih_f    = (const float*)d_in[4];
    const float* whh_f    = (const float*)d_in[5];
    const float* bih_f    = (const float*)d_in[6];
    const float* bhh_f    = (const float*)d_in[7];
    const float* wih_b    = (const float*)d_in[8];
    const float* whh_b    = (const float*)d_in[9];
    const float* bih_b    = (const float*)d_in[10];
    const float* bhh_b    = (const float*)d_in[11];
    const float* b1       = (const float*)d_in[13];
    const float* b2       = (const float*)d_in[15];
    const float* bf       = (const float*)d_in[17];
    float* out = (float*)d_out;

    float *pX, *pxg, *pWt, *pBias, *pW1t, *pW2t, *pWft, *pPool, *pX1, *pX2, *pLogits;
    cudaGetSymbolAddress((void**)&pX, g_X);
    cudaGetSymbolAddress((void**)&pxg, g_xg);
    cudaGetSymbolAddress((void**)&pWt, g_Wt);
    cudaGetSymbolAddress((void**)&pBias, g_bias);
    cudaGetSymbolAddress((void**)&pW1t, g_W1t);
    cudaGetSymbolAddress((void**)&pW2t, g_W2t);
    cudaGetSymbolAddress((void**)&pWft, g_Wft);
    cudaGetSymbolAddress((void**)&pPool, g_pool);
    cudaGetSymbolAddress((void**)&pX1, g_x1);
    cudaGetSymbolAddress((void**)&pX2, g_x2);
    cudaGetSymbolAddress((void**)&pLogits, g_logits);

    static int smem_set = 0;
    int recur_smem = (24 * WSTR + 64 * HSTR + 64 * 25 + 64 * 25 + 64 * 6 + 64 * 6) * 4;
    if (!smem_set) {
        cudaFuncSetAttribute(k_recur, cudaFuncAttributeMaxDynamicSharedMemorySize, recur_smem);
        smem_set = 1;
    }

    k_prep<<<512, 256>>>(wih_f, wih_b, bih_f, bhh_f, bih_b, bhh_b,
                         (const float*)d_in[12], (const float*)d_in[14], (const float*)d_in[16]);
    k_gather<<<2048, 256>>>(sentence, aspect, emb);

    dim3 ggrid(MROWS / BM, G4 / BN);
    k_gemm<<<ggrid, 256>>>(pX, KP, pWt, G4, pBias, pxg, G4, MROWS, G4, KP, 0);
    k_gemm<<<ggrid, 256>>>(pX, KP, pWt + (size_t)KP * G4, G4, pBias + G4,
                           pxg + (size_t)MROWS * G4, G4, MROWS, G4, KP, 0);

    k_recur<<<128, 256, recur_smem>>>(whh_f, whh_b);

    k_dots<<<dim3(NBATCH, LSEQ / 8), 256>>>();
    k_softmax<<<NBATCH, 256>>>(text_len);
    k_pool<<<NBATCH, 256>>>();

    k_gemm<<<dim3(1, FIN / BN), 256>>>(pPool, DFEAT, pW1t, FIN, b1, pX1, FIN, NBATCH, FIN, DFEAT, 1);
    k_gemm<<<dim3(1, FIN / BN), 256>>>(pX1, FIN, pW2t, FIN, b2, pX2, FIN, NBATCH, FIN, FIN, 1);
    k_gemm<<<dim3(1, 1), 256>>>(pX2, FIN, pWft, 128, bf, pLogits, NCLS, NBATCH, NCLS, FIN, 0);

    k_out<<<4096, 256>>>(out);
}